// round 4
// baseline (speedup 1.0000x reference)
#include <cuda_runtime.h>
#include <cuda_bf16.h>
#include <math_constants.h>

// Problem constants
#define BATCH 4
#define SEQ   2048
#define DMODEL 1024
#define NHEAD 16
#define HEADDIM 64
#define ROWS (BATCH * SEQ)          // 8192
#define QKV_COLS (3 * DMODEL)       // 3072

// Scratch (device globals: allocation-free per harness rules)
__device__ float g_qkv[(size_t)ROWS * QKV_COLS];  // [B*L, 3D]
__device__ float g_y[(size_t)ROWS * DMODEL];      // [B*L, D]

// ---------------------------------------------------------------------------
// SGEMM: C[M,N] = A[M,K] @ B[K,N], row-major, all dims multiples of tile.
// 128x128 block, BK=8, 256 threads, 8x8 per thread.
// ---------------------------------------------------------------------------
#define BM 128
#define BN 128
#define BK 8
#define TM 8
#define TN 8

__global__ __launch_bounds__(256) void sgemm_kernel(
    const float* __restrict__ A, const float* __restrict__ B,
    float* __restrict__ C, int M, int N, int K)
{
    __shared__ float As[BK][BM];
    __shared__ float Bs[BK][BN];

    const int block_row = blockIdx.y * BM;
    const int block_col = blockIdx.x * BN;
    const int tid = threadIdx.x;
    const int tx = tid & 15;           // 0..15
    const int ty = tid >> 4;           // 0..15

    float acc[TM][TN];
    #pragma unroll
    for (int i = 0; i < TM; i++)
        #pragma unroll
        for (int j = 0; j < TN; j++) acc[i][j] = 0.f;

    const int arow = tid >> 1;          // 0..127
    const int ak   = (tid & 1) * 4;     // 0 or 4
    const int brow = tid >> 5;          // 0..7
    const int bcol = (tid & 31) * 4;    // 0..124

    for (int k0 = 0; k0 < K; k0 += BK) {
        // Load A tile (BM x BK), store transposed
        float4 av = *(const float4*)&A[(size_t)(block_row + arow) * K + k0 + ak];
        As[ak + 0][arow] = av.x;
        As[ak + 1][arow] = av.y;
        As[ak + 2][arow] = av.z;
        As[ak + 3][arow] = av.w;
        // Load B tile (BK x BN)
        *(float4*)&Bs[brow][bcol] =
            *(const float4*)&B[(size_t)(k0 + brow) * N + block_col + bcol];
        __syncthreads();

        #pragma unroll
        for (int kk = 0; kk < BK; kk++) {
            float a[TM], b[TN];
            #pragma unroll
            for (int i = 0; i < TM; i += 4) {
                float4 t = *(const float4*)&As[kk][ty * TM + i];
                a[i] = t.x; a[i+1] = t.y; a[i+2] = t.z; a[i+3] = t.w;
            }
            #pragma unroll
            for (int j = 0; j < TN; j += 4) {
                float4 t = *(const float4*)&Bs[kk][tx * TN + j];
                b[j] = t.x; b[j+1] = t.y; b[j+2] = t.z; b[j+3] = t.w;
            }
            #pragma unroll
            for (int i = 0; i < TM; i++)
                #pragma unroll
                for (int j = 0; j < TN; j++)
                    acc[i][j] = fmaf(a[i], b[j], acc[i][j]);
        }
        __syncthreads();
    }

    #pragma unroll
    for (int i = 0; i < TM; i++) {
        float* crow = &C[(size_t)(block_row + ty * TM + i) * N + block_col + tx * TN];
        #pragma unroll
        for (int j = 0; j < TN; j += 4) {
            float4 t; t.x = acc[i][j]; t.y = acc[i][j+1]; t.z = acc[i][j+2]; t.w = acc[i][j+3];
            *(float4*)&crow[j] = t;
        }
    }
}

// ---------------------------------------------------------------------------
// Flash attention (causal, fp32). One block = (q-tile of 64 rows, one b*h).
// 64 threads; thread t owns q row (qtile*64 + t). K/V tiles in smem (padded).
// Online softmax processed in 16-wide chunks to cap register pressure.
// ---------------------------------------------------------------------------
#define KPAD 68   // 64 + 4 pad: kills the 256B-stride store conflicts, keeps 16B align

__global__ __launch_bounds__(64) void attn_kernel(
    const float* __restrict__ qkv, float* __restrict__ y)
{
    __shared__ float Ks[64][KPAD];
    __shared__ float Vs[64][KPAD];

    const int qtile = blockIdx.x;        // 0..31
    const int bh = blockIdx.y;           // 0..63
    const int b = bh >> 4;               // /NHEAD
    const int h = bh & 15;
    const int t = threadIdx.x;           // 0..63
    const int qrow = qtile * 64 + t;     // global q index within seq

    const float scale = 0.125f;          // 1/sqrt(64)

    // Load this thread's q row (scaled)
    float q[HEADDIM];
    {
        const float* qp = qkv + ((size_t)(b * SEQ + qrow)) * QKV_COLS + h * HEADDIM;
        #pragma unroll
        for (int d = 0; d < HEADDIM; d += 4) {
            float4 v = *(const float4*)(qp + d);
            q[d] = v.x * scale; q[d+1] = v.y * scale;
            q[d+2] = v.z * scale; q[d+3] = v.w * scale;
        }
    }

    float m = -CUDART_INF_F;
    float l = 0.f;
    float o[HEADDIM];
    #pragma unroll
    for (int d = 0; d < HEADDIM; d++) o[d] = 0.f;

    for (int kt = 0; kt <= qtile; kt++) {
        // Cooperative load: thread t loads K/V row t of this tile
        {
            const float* kp = qkv + ((size_t)(b * SEQ + kt * 64 + t)) * QKV_COLS
                              + DMODEL + h * HEADDIM;
            const float* vp = kp + DMODEL;
            #pragma unroll
            for (int d = 0; d < HEADDIM; d += 4) {
                *(float4*)&Ks[t][d] = *(const float4*)(kp + d);
                *(float4*)&Vs[t][d] = *(const float4*)(vp + d);
            }
        }
        __syncthreads();

        const bool diag = (kt == qtile);

        #pragma unroll 1
        for (int jc = 0; jc < 64; jc += 16) {
            float s[16];
            float cmax = -CUDART_INF_F;
            #pragma unroll
            for (int jj = 0; jj < 16; jj++) {
                const int j = jc + jj;
                float a0 = 0.f, a1 = 0.f;
                #pragma unroll
                for (int d = 0; d < HEADDIM; d += 8) {
                    float4 k0 = *(const float4*)&Ks[j][d];
                    float4 k1 = *(const float4*)&Ks[j][d + 4];
                    a0 = fmaf(q[d+0], k0.x, a0); a0 = fmaf(q[d+1], k0.y, a0);
                    a0 = fmaf(q[d+2], k0.z, a0); a0 = fmaf(q[d+3], k0.w, a0);
                    a1 = fmaf(q[d+4], k1.x, a1); a1 = fmaf(q[d+5], k1.y, a1);
                    a1 = fmaf(q[d+6], k1.z, a1); a1 = fmaf(q[d+7], k1.w, a1);
                }
                float acc = a0 + a1;
                if (diag && (kt * 64 + j > qrow)) acc = -CUDART_INF_F;
                s[jj] = acc;
                cmax = fmaxf(cmax, acc);
            }

            const float mnew = fmaxf(m, cmax);
            // mnew is finite from the very first chunk (k index 0 is always
            // unmasked), so exp(m - mnew) is well-defined thereafter; for the
            // first chunk m=-inf gives corr=0 with o already zero.
            const float corr = __expf(m - mnew);
            m = mnew;
            l *= corr;
            #pragma unroll
            for (int d = 0; d < HEADDIM; d++) o[d] *= corr;

            #pragma unroll
            for (int jj = 0; jj < 16; jj++) {
                const int j = jc + jj;
                const float p = __expf(s[jj] - mnew);  // masked -> exp(-inf)=0
                l += p;
                #pragma unroll
                for (int d = 0; d < HEADDIM; d += 4) {
                    float4 vv = *(const float4*)&Vs[j][d];
                    o[d+0] = fmaf(p, vv.x, o[d+0]);
                    o[d+1] = fmaf(p, vv.y, o[d+1]);
                    o[d+2] = fmaf(p, vv.z, o[d+2]);
                    o[d+3] = fmaf(p, vv.w, o[d+3]);
                }
            }
        }
        __syncthreads();
    }

    // Epilogue: y[b, qrow, h*64 + d] = o[d] / l
    const float inv = 1.f / l;
    float* yp = y + ((size_t)(b * SEQ + qrow)) * DMODEL + h * HEADDIM;
    #pragma unroll
    for (int d = 0; d < HEADDIM; d += 4) {
        float4 v;
        v.x = o[d+0] * inv; v.y = o[d+1] * inv;
        v.z = o[d+2] * inv; v.w = o[d+3] * inv;
        *(float4*)(yp + d) = v;
    }
}

// ---------------------------------------------------------------------------
// Launch
// ---------------------------------------------------------------------------
extern "C" void kernel_launch(void* const* d_in, const int* in_sizes, int n_in,
                              void* d_out, int out_size)
{
    const float* x     = (const float*)d_in[0];   // [B, L, D]
    const float* Wqkv  = (const float*)d_in[1];   // [D, 3D]
    const float* Wproj = (const float*)d_in[2];   // [D, D]
    float* out = (float*)d_out;                   // [B, L, D]
    (void)in_sizes; (void)n_in; (void)out_size;

    float* qkv = nullptr;
    float* y = nullptr;
    cudaGetSymbolAddress((void**)&qkv, g_qkv);
    cudaGetSymbolAddress((void**)&y, g_y);

    // 1) qkv = x @ Wqkv : [8192,1024] @ [1024,3072]
    sgemm_kernel<<<dim3(QKV_COLS / BN, ROWS / BM), 256>>>(x, Wqkv, qkv, ROWS, QKV_COLS, DMODEL);

    // 2) fused causal attention -> y [8192,1024]
    attn_kernel<<<dim3(SEQ / 64, BATCH * NHEAD), 64>>>(qkv, y);

    // 3) out = y @ Wproj : [8192,1024] @ [1024,1024]
    sgemm_kernel<<<dim3(DMODEL / BN, ROWS / BM), 256>>>(y, Wproj, out, ROWS, DMODEL, DMODEL);
}